// round 1
// baseline (speedup 1.0000x reference)
#include <cuda_runtime.h>
#include <cstdint>
#include <cstdio>

// Problem constants
#define NN   384
#define HH   128
#define LATD 64
#define RR   16
#define LL   3
#define TT   64      // j-tile size
#define USs  148     // us row stride (pad vs 144 to avoid bank conflicts)
#define MSs  132     // m1s/ms row stride
#define CUT2 144.0f
#define GAMMA 1.7777778f   // (16/12)^2
#define MUSTEP 0.8f        // 12/15

// ---------------- device scratch (no allocation allowed) ----------------
__device__ float g_h[NN * HH];
__device__ float g_x[NN * 3];
__device__ float g_agg[NN * HH];
__device__ float g_xupd[NN * 3];

__device__ __forceinline__ float silu_f(float v) {
    return __fdividef(v, 1.0f + __expf(-v));
}

// ---------------- initial kernels ----------------
__global__ void k_center(const float* __restrict__ a) {
    __shared__ float sx[NN], sy[NN], sz[NN];
    __shared__ float mean[3];
    int i = threadIdx.x;
    sx[i] = a[i * 3 + 0];
    sy[i] = a[i * 3 + 1];
    sz[i] = a[i * 3 + 2];
    __syncthreads();
    if (i < 3) {
        const float* s = (i == 0) ? sx : (i == 1) ? sy : sz;
        float t = 0.f;
        for (int k = 0; k < NN; k++) t += s[k];
        mean[i] = t / (float)NN;
    }
    __syncthreads();
    g_x[i * 3 + 0] = sx[i] - mean[0];
    g_x[i * 3 + 1] = sy[i] - mean[1];
    g_x[i * 3 + 2] = sz[i] - mean[2];
}

__global__ void k_proj(const float* __restrict__ z, const float* __restrict__ W,
                       const float* __restrict__ b) {
    __shared__ float zr[LATD];
    int i = blockIdx.x, c = threadIdx.x;
    if (c < LATD) zr[c] = z[i * LATD + c];
    __syncthreads();
    float acc = b[c];
#pragma unroll 8
    for (int k = 0; k < LATD; k++) acc = fmaf(zr[k], W[k * HH + c], acc);
    g_h[i * HH + c] = acc;
}

// ---------------- register-tiled smem GEMM + silu ----------------
// Computes dst[j][c] = silu(sum_k u[j][k] * wb[k][c] + bias[c]) for a TTx128 tile.
// 256 threads: thread owns 8 j's x 4 c's. All lanes of a warp share the j-group,
// so u loads are smem broadcasts; weight loads are float4.
template <int K>
__device__ __forceinline__ void gemm_silu(const float* __restrict__ u, int ustr,
                                          const float* __restrict__ wb,
                                          const float* __restrict__ bias,
                                          float* __restrict__ dst, int dstr, int tid) {
    const int jg = (tid >> 5) * 8;
    const int cg = (tid & 31) * 4;
    float acc[8][4];
#pragma unroll
    for (int jj = 0; jj < 8; jj++)
#pragma unroll
        for (int q = 0; q < 4; q++) acc[jj][q] = 0.f;

    const float* urow = u + jg * ustr;
#pragma unroll 4
    for (int k = 0; k < K; k++) {
        float4 w4 = *reinterpret_cast<const float4*>(wb + k * HH + cg);
#pragma unroll
        for (int jj = 0; jj < 8; jj++) {
            float uv = urow[jj * ustr + k];
            acc[jj][0] = fmaf(uv, w4.x, acc[jj][0]);
            acc[jj][1] = fmaf(uv, w4.y, acc[jj][1]);
            acc[jj][2] = fmaf(uv, w4.z, acc[jj][2]);
            acc[jj][3] = fmaf(uv, w4.w, acc[jj][3]);
        }
    }
    float b0 = bias[cg + 0], b1 = bias[cg + 1], b2 = bias[cg + 2], b3 = bias[cg + 3];
#pragma unroll
    for (int jj = 0; jj < 8; jj++) {
        float* d = dst + (jg + jj) * dstr + cg;
        d[0] = silu_f(acc[jj][0] + b0);
        d[1] = silu_f(acc[jj][1] + b1);
        d[2] = silu_f(acc[jj][2] + b2);
        d[3] = silu_f(acc[jj][3] + b3);
    }
}

// ---------------- edge kernel: one CTA per receiver node ----------------
// smem float layout sizes
#define SM_FLOATS (NN * 3 + HH + HH + HH + HH + NN + HH + TT * 3 + 4 + TT * USs + 144 * HH + TT * MSs + TT * MSs)
#define SM_INTS   (NN + 8 + 8 + 4)
#define SMEM_BYTES ((SM_FLOATS + SM_INTS) * 4)

__global__ __launch_bounds__(256, 1) void k_edge(
    const float* __restrict__ eW1, const float* __restrict__ eb1,
    const float* __restrict__ eW2, const float* __restrict__ eb2,
    const float* __restrict__ cW1, const float* __restrict__ cb1,
    const float* __restrict__ cW2, int l) {
    extern __shared__ float sm[];
    float* xs    = sm;                 // NN*3
    float* hi_s  = xs + NN * 3;        // HH
    float* base1 = hi_s + HH;          // HH   (hi part of GEMM1 + eb1)
    float* bias_s = base1 + HH;        // HH
    float* cW2s  = bias_s + HH;        // HH
    float* dlist = cW2s + HH;          // NN
    float* aggs  = dlist + NN;         // HH
    float* cont  = aggs + HH;          // TT*3
    float* xacc  = cont + TT * 3;      // 4
    float* us    = xacc + 4;           // TT*USs  ([hj | rbf] tile)
    float* wb    = us + TT * USs;      // 144*HH  (weight staging)
    float* m1s   = wb + 144 * HH;      // TT*MSs
    float* ms    = m1s + TT * MSs;     // TT*MSs
    int* nbr    = (int*)(ms + TT * MSs);  // NN
    int* wcnt   = nbr + NN;               // 8
    int* wbase  = wcnt + 8;               // 8
    int* misc   = wbase + 8;              // 4

    const int i = blockIdx.x, tid = threadIdx.x;
    const int lane = tid & 31, wrp = tid >> 5;

    for (int t = tid; t < NN * 3; t += 256) xs[t] = g_x[t];
    if (tid < HH) {
        hi_s[tid] = g_h[i * HH + tid];
        cW2s[tid] = cW2[l * HH + tid];
        aggs[tid] = 0.f;
    }
    if (tid == 0) { misc[0] = 0; xacc[0] = 0.f; xacc[1] = 0.f; xacc[2] = 0.f; }
    __syncthreads();

    const float xi0 = xs[i * 3 + 0], xi1 = xs[i * 3 + 1], xi2 = xs[i * 3 + 2];

    // base1[c] = eb1[c] + sum_k hi[k] * eW1[k][c]   (receiver-invariant)
    if (tid < HH) {
        float acc = eb1[l * HH + tid];
        const float* W = eW1 + (size_t)l * 272 * HH + tid;
#pragma unroll 4
        for (int k = 0; k < HH; k++) acc = fmaf(hi_s[k], W[k * HH], acc);
        base1[tid] = acc;
    }

    // --- deterministic ordered compaction of masked neighbors ---
    for (int base = 0; base < NN; base += 256) {
        int j = base + tid;
        bool p = false;
        float d2 = 0.f;
        if (j < NN && j != i) {
            float dx = xi0 - xs[j * 3 + 0];
            float dy = xi1 - xs[j * 3 + 1];
            float dz = xi2 - xs[j * 3 + 2];
            d2 = dx * dx + dy * dy + dz * dz;
            p = (d2 < CUT2) || (j == i - 1) || (j == i + 1);
        }
        unsigned bal = __ballot_sync(0xffffffffu, p);
        if (lane == 0) wcnt[wrp] = __popc(bal);
        __syncthreads();
        if (tid == 0) {
            int run = misc[0];
            for (int q = 0; q < 8; q++) { wbase[q] = run; run += wcnt[q]; }
            misc[0] = run;
        }
        __syncthreads();
        if (p) {
            int pos = wbase[wrp] + __popc(bal & ((1u << lane) - 1u));
            nbr[pos] = j;
            dlist[pos] = sqrtf(d2);
        }
        __syncthreads();
    }
    const int cnt = misc[0];

    // --- tile loop over neighbors ---
    for (int t0 = 0; t0 < cnt; t0 += TT) {
        const int tc = min(TT, cnt - t0);

        // stage [hj | rbf] tile (padding rows = 0)
        for (int idx = tid; idx < TT * HH; idx += 256) {
            int jj = idx >> 7, c = idx & 127;
            float v = 0.f;
            if (jj < tc) v = g_h[nbr[t0 + jj] * HH + c];
            us[jj * USs + c] = v;
        }
        for (int idx = tid; idx < TT * RR; idx += 256) {
            int jj = idx >> 4, r = idx & 15;
            float v = 0.f;
            if (jj < tc) {
                float dd = dlist[t0 + jj] - MUSTEP * (float)r;
                v = __expf(-GAMMA * dd * dd);
            }
            us[jj * USs + HH + r] = v;
        }
        // stage eW1 rows [128..272) (hj + rbf part)
        {
            const float* W = eW1 + ((size_t)l * 272 + HH) * HH;
            for (int idx = tid; idx < 144 * HH; idx += 256) wb[idx] = W[idx];
        }
        __syncthreads();

        gemm_silu<144>(us, USs, wb, base1, m1s, MSs, tid);   // m1
        __syncthreads();

        {
            const float* W = eW2 + (size_t)l * HH * HH;
            for (int idx = tid; idx < HH * HH; idx += 256) wb[idx] = W[idx];
            if (tid < HH) bias_s[tid] = eb2[l * HH + tid];
        }
        __syncthreads();

        gemm_silu<128>(m1s, MSs, wb, bias_s, ms, MSs, tid);  // m
        __syncthreads();

        // agg accumulation (deterministic serial over tile) + stage cW1
        {
            const float* W = cW1 + (size_t)l * HH * HH;
            for (int idx = tid; idx < HH * HH; idx += 256) wb[idx] = W[idx];
            if (tid < HH) {
                float s = 0.f;
                for (int jj = 0; jj < tc; jj++) s += ms[jj * MSs + tid];
                aggs[tid] += s;
                bias_s[tid] = cb1[l * HH + tid];
            }
        }
        __syncthreads();

        gemm_silu<128>(ms, MSs, wb, bias_s, m1s, MSs, tid);  // c1 (reuse m1s)
        __syncthreads();

        // per-edge scalar w and coord contribution
        if (tid < tc) {
            float s = 0.f;
#pragma unroll 4
            for (int c = 0; c < HH; c++) s = fmaf(m1s[tid * MSs + c], cW2s[c], s);
            int j = nbr[t0 + tid];
            cont[tid * 3 + 0] = (xi0 - xs[j * 3 + 0]) * s;
            cont[tid * 3 + 1] = (xi1 - xs[j * 3 + 1]) * s;
            cont[tid * 3 + 2] = (xi2 - xs[j * 3 + 2]) * s;
        }
        __syncthreads();
        if (tid < 3) {
            float s = xacc[tid];
            for (int jj = 0; jj < tc; jj++) s += cont[jj * 3 + tid];
            xacc[tid] = s;
        }
        __syncthreads();
    }

    if (tid < HH) g_agg[i * HH + tid] = aggs[tid];
    if (tid < 3) g_xupd[i * 3 + tid] = xacc[tid];
}

// ---------------- node update kernel ----------------
__global__ void k_node(const float* __restrict__ nW1, const float* __restrict__ nb1,
                       const float* __restrict__ nW2, const float* __restrict__ nb2,
                       int l) {
    __shared__ float hrow[HH], arow[HH], n1[HH];
    int i = blockIdx.x, c = threadIdx.x;
    hrow[c] = g_h[i * HH + c];
    arow[c] = g_agg[i * HH + c];
    __syncthreads();
    const float* W1 = nW1 + (size_t)l * 256 * HH;
    float acc = nb1[l * HH + c];
#pragma unroll 4
    for (int k = 0; k < HH; k++) acc = fmaf(hrow[k], W1[k * HH + c], acc);
#pragma unroll 4
    for (int k = 0; k < HH; k++) acc = fmaf(arow[k], W1[(HH + k) * HH + c], acc);
    n1[c] = silu_f(acc);
    __syncthreads();
    const float* W2 = nW2 + (size_t)l * HH * HH;
    float o = hrow[c] + nb2[l * HH + c];
#pragma unroll 4
    for (int k = 0; k < HH; k++) o = fmaf(n1[k], W2[k * HH + c], o);
    g_h[i * HH + c] = o;
    if (c < 3) g_x[i * 3 + c] += g_xupd[i * 3 + c];
}

__global__ void k_out(float* __restrict__ out) {
    int t = blockIdx.x * blockDim.x + threadIdx.x;
    if (t < NN * 3) out[t] = g_x[t];
}

// ---------------- launch ----------------
extern "C" void kernel_launch(void* const* d_in, const int* in_sizes, int n_in,
                              void* d_out, int out_size) {
    const float* z      = (const float*)d_in[0];
    const float* anchor = (const float*)d_in[1];
    const float* proj_W = (const float*)d_in[2];
    const float* proj_b = (const float*)d_in[3];
    const float* eW1    = (const float*)d_in[4];
    const float* eb1    = (const float*)d_in[5];
    const float* eW2    = (const float*)d_in[6];
    const float* eb2    = (const float*)d_in[7];
    const float* nW1    = (const float*)d_in[8];
    const float* nb1    = (const float*)d_in[9];
    const float* nW2    = (const float*)d_in[10];
    const float* nb2    = (const float*)d_in[11];
    const float* cW1    = (const float*)d_in[12];
    const float* cb1    = (const float*)d_in[13];
    const float* cW2    = (const float*)d_in[14];

    cudaFuncSetAttribute(k_edge, cudaFuncAttributeMaxDynamicSharedMemorySize, SMEM_BYTES);

    k_center<<<1, NN>>>(anchor);
    k_proj<<<NN, HH>>>(z, proj_W, proj_b);
    for (int l = 0; l < LL; l++) {
        k_edge<<<NN, 256, SMEM_BYTES>>>(eW1, eb1, eW2, eb2, cW1, cb1, cW2, l);
        k_node<<<NN, HH>>>(nW1, nb1, nW2, nb2, l);
    }
    k_out<<<(NN * 3 + 255) / 256, 256>>>((float*)d_out);
}

// round 2
// speedup vs baseline: 1.3238x; 1.3238x over previous
#include <cuda_runtime.h>
#include <cstdint>

// Problem constants
#define NN   384
#define HH   128
#define LATD 64
#define RR   16
#define LL   3
#define TT   64      // j-tile size
#define USs  148     // us row stride (even, row byte-stride 592 = 37*16)
#define MSs  132     // m1s/ms row stride (even, 528 = 33*16)
#define RBB  16      // rows per CTA in k_base/k_node
#define CUT2 144.0f
#define GAMMA 1.7777778f   // (16/12)^2
#define MUSTEP 0.8f        // 12/15

typedef unsigned long long u64;

// ---------------- device scratch ----------------
__device__ float g_h[NN * HH];
__device__ float g_x[NN * 3];
__device__ float g_agg[NN * HH];
__device__ float g_xupd[NN * 3];
__device__ float g_base1[NN * HH];

__device__ __forceinline__ float silu_f(float v) {
    return __fdividef(v, 1.0f + __expf(-v));
}
__device__ __forceinline__ u64 pk2(float x, float y) {
    u64 r; asm("mov.b64 %0,{%1,%2};" : "=l"(r) : "f"(x), "f"(y)); return r;
}
__device__ __forceinline__ u64 fma2(u64 a, u64 b, u64 c) {
    u64 d; asm("fma.rn.f32x2 %0,%1,%2,%3;" : "=l"(d) : "l"(a), "l"(b), "l"(c)); return d;
}
__device__ __forceinline__ float2 upk(u64 a) {
    float2 f; asm("mov.b64 {%0,%1},%2;" : "=f"(f.x), "=f"(f.y) : "l"(a)); return f;
}
__device__ __forceinline__ void cpa16(float* s, const float* g) {
    unsigned sa = (unsigned)__cvta_generic_to_shared(s);
    asm volatile("cp.async.cg.shared.global [%0], [%1], 16;" :: "r"(sa), "l"(g));
}
__device__ __forceinline__ void cpa_commit() { asm volatile("cp.async.commit_group;"); }
template <int W> __device__ __forceinline__ void cpa_wait() {
    asm volatile("cp.async.wait_group %0;" :: "n"(W) : "memory");
}
__device__ __forceinline__ void stage_async(float* dst, const float* src, int nfl, int tid) {
    for (int i = tid * 4; i < nfl; i += 1024) cpa16(dst + i, src + i);
}

// ---------------- initial kernels ----------------
__global__ void k_center(const float* __restrict__ a) {
    __shared__ float sx[NN], sy[NN], sz[NN];
    __shared__ float mean[3];
    int i = threadIdx.x;
    sx[i] = a[i * 3 + 0]; sy[i] = a[i * 3 + 1]; sz[i] = a[i * 3 + 2];
    __syncthreads();
    if (i < 3) {
        const float* s = (i == 0) ? sx : (i == 1) ? sy : sz;
        float t = 0.f;
        for (int k = 0; k < NN; k++) t += s[k];
        mean[i] = t / (float)NN;
    }
    __syncthreads();
    g_x[i * 3 + 0] = sx[i] - mean[0];
    g_x[i * 3 + 1] = sy[i] - mean[1];
    g_x[i * 3 + 2] = sz[i] - mean[2];
}

__global__ void k_proj(const float* __restrict__ z, const float* __restrict__ W,
                       const float* __restrict__ b) {
    __shared__ float zr[LATD];
    int i = blockIdx.x, c = threadIdx.x;
    if (c < LATD) zr[c] = z[i * LATD + c];
    __syncthreads();
    float acc = b[c];
#pragma unroll 8
    for (int k = 0; k < LATD; k++) acc = fmaf(zr[k], W[k * HH + c], acc);
    g_h[i * HH + c] = acc;
}

// ---------------- single-row f32x2 GEMM helper (K=128) ----------------
__device__ __forceinline__ void gemm_row128(u64 acc[4], const float* __restrict__ u0,
                                            const float* __restrict__ w, int cg) {
#pragma unroll 4
    for (int k = 0; k < HH; k += 2) {
        ulonglong2 w0a = *(const ulonglong2*)(w + k * HH + cg);
        ulonglong2 w0b = *(const ulonglong2*)(w + k * HH + cg + 4);
        ulonglong2 w1a = *(const ulonglong2*)(w + (k + 1) * HH + cg);
        ulonglong2 w1b = *(const ulonglong2*)(w + (k + 1) * HH + cg + 4);
        float2 uv = *(const float2*)(u0 + k);
        u64 ua = pk2(uv.x, uv.x), ub = pk2(uv.y, uv.y);
        acc[0] = fma2(ua, w0a.x, acc[0]); acc[1] = fma2(ua, w0a.y, acc[1]);
        acc[2] = fma2(ua, w0b.x, acc[2]); acc[3] = fma2(ua, w0b.y, acc[3]);
        acc[0] = fma2(ub, w1a.x, acc[0]); acc[1] = fma2(ub, w1a.y, acc[1]);
        acc[2] = fma2(ub, w1b.x, acc[2]); acc[3] = fma2(ub, w1b.y, acc[3]);
    }
}

// ---------------- k_base: g_base1 = eb1 + h @ eW1[0:128] ----------------
#define SB_BASE ((HH * HH + RBB * HH + HH) * 4)
__global__ __launch_bounds__(256, 2) void k_base(const float* __restrict__ eW1,
                                                 const float* __restrict__ eb1, int l) {
    extern __shared__ float sb[];
    float* ws = sb;
    float* hs = ws + HH * HH;
    float* bs = hs + RBB * HH;
    int tid = threadIdx.x;
    int r0 = blockIdx.x * RBB;
    stage_async(ws, eW1 + (size_t)l * 272 * HH, HH * HH, tid);
    cpa_commit();
    for (int idx = tid; idx < RBB * HH / 4; idx += 256)
        *(float4*)(hs + idx * 4) = *(const float4*)(g_h + r0 * HH + idx * 4);
    if (tid < HH) bs[tid] = eb1[l * HH + tid];
    cpa_wait<0>();
    __syncthreads();
    int r = tid >> 4, cg = (tid & 15) * 8;
    const u64* bp = (const u64*)(bs + cg);
    u64 acc[4] = {bp[0], bp[1], bp[2], bp[3]};
    gemm_row128(acc, hs + r * HH, ws, cg);
    float* d = g_base1 + (r0 + r) * HH + cg;
    float2 t; float4 o0, o1;
    t = upk(acc[0]); o0.x = t.x; o0.y = t.y;
    t = upk(acc[1]); o0.z = t.x; o0.w = t.y;
    t = upk(acc[2]); o1.x = t.x; o1.y = t.y;
    t = upk(acc[3]); o1.z = t.x; o1.w = t.y;
    *(float4*)d = o0; *(float4*)(d + 4) = o1;
}

// ---------------- tile GEMM (f32x2, 4j x 8c per thread) ----------------
// dst[j][c] = silu(sum_k u[j][k]*w[k][c] + bias[c]) for rows < roundup(tc,8)
template <int K>
__device__ __forceinline__ void gemm2x(const float* __restrict__ u, int ustr,
                                       const float* __restrict__ w,
                                       const float* __restrict__ bias,
                                       float* __restrict__ dst, int dstr,
                                       int tid, int tc) {
    if (((tid >> 5) << 3) >= tc) return;   // warp-level tail skip
    const int cg = (tid & 15) * 8;
    const int jg = (tid >> 4) * 4;
    const u64* bp = (const u64*)(bias + cg);
    u64 b0 = bp[0], b1 = bp[1], b2 = bp[2], b3 = bp[3];
    u64 acc[4][4];
#pragma unroll
    for (int jj = 0; jj < 4; jj++) {
        acc[jj][0] = b0; acc[jj][1] = b1; acc[jj][2] = b2; acc[jj][3] = b3;
    }
    const float* u0 = u + jg * ustr;
#pragma unroll 4
    for (int k = 0; k < K; k += 2) {
        ulonglong2 w0a = *(const ulonglong2*)(w + k * HH + cg);
        ulonglong2 w0b = *(const ulonglong2*)(w + k * HH + cg + 4);
        ulonglong2 w1a = *(const ulonglong2*)(w + (k + 1) * HH + cg);
        ulonglong2 w1b = *(const ulonglong2*)(w + (k + 1) * HH + cg + 4);
#pragma unroll
        for (int jj = 0; jj < 4; jj++) {
            float2 uv = *(const float2*)(u0 + jj * ustr + k);
            u64 ua = pk2(uv.x, uv.x), ub = pk2(uv.y, uv.y);
            acc[jj][0] = fma2(ua, w0a.x, acc[jj][0]);
            acc[jj][1] = fma2(ua, w0a.y, acc[jj][1]);
            acc[jj][2] = fma2(ua, w0b.x, acc[jj][2]);
            acc[jj][3] = fma2(ua, w0b.y, acc[jj][3]);
            acc[jj][0] = fma2(ub, w1a.x, acc[jj][0]);
            acc[jj][1] = fma2(ub, w1a.y, acc[jj][1]);
            acc[jj][2] = fma2(ub, w1b.x, acc[jj][2]);
            acc[jj][3] = fma2(ub, w1b.y, acc[jj][3]);
        }
    }
#pragma unroll
    for (int jj = 0; jj < 4; jj++) {
        float* d = dst + (jg + jj) * dstr + cg;
        float2 t; float4 o0, o1;
        t = upk(acc[jj][0]); o0.x = silu_f(t.x); o0.y = silu_f(t.y);
        t = upk(acc[jj][1]); o0.z = silu_f(t.x); o0.w = silu_f(t.y);
        t = upk(acc[jj][2]); o1.x = silu_f(t.x); o1.y = silu_f(t.y);
        t = upk(acc[jj][3]); o1.z = silu_f(t.x); o1.w = silu_f(t.y);
        *(float4*)(d) = o0; *(float4*)(d + 4) = o1;
    }
}

// ---------------- edge kernel: one CTA per receiver ----------------
#define SM_FLOATS (144*HH + HH*HH + TT*USs + TT*MSs + NN*3 + 4*HH + NN + HH + TT*3 + 4)
#define SM_INTS   (NN + 8 + 8 + 4)
#define SMEM_EDGE ((SM_FLOATS + SM_INTS) * 4)

__global__ __launch_bounds__(256, 1) void k_edge(
    const float* __restrict__ eW1, const float* __restrict__ eW2,
    const float* __restrict__ eb2, const float* __restrict__ cW1,
    const float* __restrict__ cb1, const float* __restrict__ cW2, int l) {
    extern __shared__ float sm[];
    float* wb    = sm;                  // 144*HH   (eW1 hj+rbf part / cW1)
    float* wb2   = wb + 144 * HH;       // HH*HH    (eW2)
    float* us    = wb2 + HH * HH;       // TT*USs   ([hj|rbf] tile; also ms)
    float* m1s   = us + TT * USs;       // TT*MSs
    float* xs    = m1s + TT * MSs;      // NN*3
    float* base1 = xs + NN * 3;         // HH
    float* eb2s  = base1 + HH;          // HH
    float* cb1s  = eb2s + HH;           // HH
    float* cW2s  = cb1s + HH;           // HH
    float* dlist = cW2s + HH;           // NN
    float* aggs  = dlist + NN;          // HH
    float* cont  = aggs + HH;           // TT*3
    float* xacc  = cont + TT * 3;       // 4
    int* nbr   = (int*)(xacc + 4);      // NN
    int* wcnt  = nbr + NN;              // 8
    int* wbase = wcnt + 8;              // 8
    int* misc  = wbase + 8;             // 4

    const int i = blockIdx.x, tid = threadIdx.x;
    const int lane = tid & 31, wrp = tid >> 5;

    const float* W1p = eW1 + ((size_t)l * 272 + HH) * HH;   // rows [128..272)
    // prefetch eW1 (group A) — overlaps everything below
    stage_async(wb, W1p, 144 * HH, tid);
    cpa_commit();

    for (int t = tid; t < NN * 3; t += 256) xs[t] = g_x[t];
    if (tid < HH) {
        base1[tid] = g_base1[i * HH + tid];
        eb2s[tid]  = eb2[l * HH + tid];
        cb1s[tid]  = cb1[l * HH + tid];
        cW2s[tid]  = cW2[l * HH + tid];
        aggs[tid]  = 0.f;
    }
    if (tid == 0) { misc[0] = 0; xacc[0] = 0.f; xacc[1] = 0.f; xacc[2] = 0.f; }
    __syncthreads();

    const float xi0 = xs[i * 3 + 0], xi1 = xs[i * 3 + 1], xi2 = xs[i * 3 + 2];

    // deterministic ordered neighbor compaction
    for (int base = 0; base < NN; base += 256) {
        int j = base + tid;
        bool p = false;
        float d2 = 0.f;
        if (j < NN && j != i) {
            float dx = xi0 - xs[j * 3 + 0];
            float dy = xi1 - xs[j * 3 + 1];
            float dz = xi2 - xs[j * 3 + 2];
            d2 = dx * dx + dy * dy + dz * dz;
            p = (d2 < CUT2) || (j == i - 1) || (j == i + 1);
        }
        unsigned bal = __ballot_sync(0xffffffffu, p);
        if (lane == 0) wcnt[wrp] = __popc(bal);
        __syncthreads();
        if (tid == 0) {
            int run = misc[0];
            for (int q = 0; q < 8; q++) { wbase[q] = run; run += wcnt[q]; }
            misc[0] = run;
        }
        __syncthreads();
        if (p) {
            int pos = wbase[wrp] + __popc(bal & ((1u << lane) - 1u));
            nbr[pos] = j;
            dlist[pos] = sqrtf(d2);
        }
        __syncthreads();
    }
    const int cnt = misc[0];

    for (int t0 = 0; t0 < cnt; t0 += TT) {
        const int tc = min(TT, cnt - t0);
        const int tcr8 = (tc + 7) & ~7;

        if (t0 > 0) { stage_async(wb, W1p, 144 * HH, tid); cpa_commit(); }

        // stage hj rows (float4), zero pad rows up to tcr8
        for (int idx = tid; idx < tcr8 * (HH / 4); idx += 256) {
            int jj = idx >> 5, c4 = (idx & 31) << 2;
            float4 v = make_float4(0.f, 0.f, 0.f, 0.f);
            if (jj < tc) v = *(const float4*)(g_h + nbr[t0 + jj] * HH + c4);
            *(float4*)(us + jj * USs + c4) = v;
        }
        // rbf columns
        for (int idx = tid; idx < tcr8 * RR; idx += 256) {
            int jj = idx >> 4, r = idx & 15;
            float v = 0.f;
            if (jj < tc) {
                float dd = dlist[t0 + jj] - MUSTEP * (float)r;
                v = __expf(-GAMMA * dd * dd);
            }
            us[jj * USs + HH + r] = v;
        }
        // prefetch eW2 (group B) while gemm1 runs
        stage_async(wb2, eW2 + (size_t)l * HH * HH, HH * HH, tid);
        cpa_commit();

        cpa_wait<1>();      // eW1 staged
        __syncthreads();

        gemm2x<144>(us, USs, wb, base1, m1s, MSs, tid, tc);   // m1

        cpa_wait<0>();      // eW2 staged
        __syncthreads();    // gemm1 done; wb free; wb2/m1s visible

        stage_async(wb, cW1 + (size_t)l * HH * HH, HH * HH, tid);  // prefetch cW1
        cpa_commit();

        gemm2x<128>(m1s, MSs, wb2, eb2s, us, MSs, tid, tc);   // m (-> us space)

        cpa_wait<0>();      // cW1 staged
        __syncthreads();    // gemm2 done; ms visible

        // agg accumulation (deterministic)
        if (tid < HH) {
            float s = 0.f;
            for (int jj = 0; jj < tc; jj++) s += us[jj * MSs + tid];
            aggs[tid] += s;
        }

        gemm2x<128>(us, MSs, wb, cb1s, m1s, MSs, tid, tc);    // c1
        __syncthreads();

        // per-edge scalar w + coord contribution
        if (tid < tc) {
            const float* mr = m1s + tid * MSs;
            float s = 0.f;
#pragma unroll 8
            for (int c = 0; c < HH; c++) s = fmaf(mr[c], cW2s[c], s);
            int j = nbr[t0 + tid];
            cont[tid * 3 + 0] = (xi0 - xs[j * 3 + 0]) * s;
            cont[tid * 3 + 1] = (xi1 - xs[j * 3 + 1]) * s;
            cont[tid * 3 + 2] = (xi2 - xs[j * 3 + 2]) * s;
        }
        __syncthreads();
        if (tid < 3) {
            float s = xacc[tid];
            for (int jj = 0; jj < tc; jj++) s += cont[jj * 3 + tid];
            xacc[tid] = s;
        }
        __syncthreads();
    }

    if (tid < HH) g_agg[i * HH + tid] = aggs[tid];
    if (tid < 3) g_xupd[i * 3 + tid] = xacc[tid];
}

// ---------------- k_node: tiled node update ----------------
#define SB_NODE ((HH*HH + 3*RBB*HH + 2*HH) * 4)
__global__ __launch_bounds__(256, 2) void k_node(
    const float* __restrict__ nW1, const float* __restrict__ nb1,
    const float* __restrict__ nW2, const float* __restrict__ nb2, int l) {
    extern __shared__ float sb[];
    float* ws  = sb;                 // HH*HH
    float* hs  = ws + HH * HH;       // RBB*HH
    float* as_ = hs + RBB * HH;      // RBB*HH
    float* n1s = as_ + RBB * HH;     // RBB*HH
    float* b1s = n1s + RBB * HH;     // HH
    float* b2s = b1s + HH;           // HH
    int tid = threadIdx.x;
    int r0 = blockIdx.x * RBB;
    const float* W1 = nW1 + (size_t)l * 2 * HH * HH;

    stage_async(ws, W1, HH * HH, tid);     // W1 h-part
    cpa_commit();
    for (int idx = tid; idx < RBB * HH / 4; idx += 256) {
        *(float4*)(hs + idx * 4)  = *(const float4*)(g_h + r0 * HH + idx * 4);
        *(float4*)(as_ + idx * 4) = *(const float4*)(g_agg + r0 * HH + idx * 4);
    }
    if (tid < HH) { b1s[tid] = nb1[l * HH + tid]; b2s[tid] = nb2[l * HH + tid]; }
    if (tid < RBB * 3) {
        int rr = tid / 3, cc = tid - rr * 3;
        g_x[(r0 + rr) * 3 + cc] += g_xupd[(r0 + rr) * 3 + cc];
    }
    cpa_wait<0>();
    __syncthreads();

    int r = tid >> 4, cg = (tid & 15) * 8;
    const u64* bp = (const u64*)(b1s + cg);
    u64 acc[4] = {bp[0], bp[1], bp[2], bp[3]};
    gemm_row128(acc, hs + r * HH, ws, cg);
    __syncthreads();                       // phase A done reading ws

    stage_async(ws, W1 + HH * HH, HH * HH, tid);  // W1 agg-part
    cpa_commit();
    cpa_wait<0>();
    __syncthreads();
    gemm_row128(acc, as_ + r * HH, ws, cg);
    {
        float* d = n1s + r * HH + cg;
        float2 t; float4 o0, o1;
        t = upk(acc[0]); o0.x = silu_f(t.x); o0.y = silu_f(t.y);
        t = upk(acc[1]); o0.z = silu_f(t.x); o0.w = silu_f(t.y);
        t = upk(acc[2]); o1.x = silu_f(t.x); o1.y = silu_f(t.y);
        t = upk(acc[3]); o1.z = silu_f(t.x); o1.w = silu_f(t.y);
        *(float4*)d = o0; *(float4*)(d + 4) = o1;
    }
    __syncthreads();                       // n1 ready; ws free

    stage_async(ws, nW2 + (size_t)l * HH * HH, HH * HH, tid);
    cpa_commit();
    cpa_wait<0>();
    __syncthreads();
    {
        const float* hr = hs + r * HH + cg;
        const float* bb = b2s + cg;
        u64 oa[4];
        oa[0] = pk2(hr[0] + bb[0], hr[1] + bb[1]);
        oa[1] = pk2(hr[2] + bb[2], hr[3] + bb[3]);
        oa[2] = pk2(hr[4] + bb[4], hr[5] + bb[5]);
        oa[3] = pk2(hr[6] + bb[6], hr[7] + bb[7]);
        gemm_row128(oa, n1s + r * HH, ws, cg);
        float* d = g_h + (r0 + r) * HH + cg;
        float2 t; float4 o0, o1;
        t = upk(oa[0]); o0.x = t.x; o0.y = t.y;
        t = upk(oa[1]); o0.z = t.x; o0.w = t.y;
        t = upk(oa[2]); o1.x = t.x; o1.y = t.y;
        t = upk(oa[3]); o1.z = t.x; o1.w = t.y;
        *(float4*)d = o0; *(float4*)(d + 4) = o1;
    }
}

__global__ void k_out(float* __restrict__ out) {
    int t = blockIdx.x * blockDim.x + threadIdx.x;
    if (t < NN * 3) out[t] = g_x[t];
}

// ---------------- launch ----------------
extern "C" void kernel_launch(void* const* d_in, const int* in_sizes, int n_in,
                              void* d_out, int out_size) {
    const float* z      = (const float*)d_in[0];
    const float* anchor = (const float*)d_in[1];
    const float* proj_W = (const float*)d_in[2];
    const float* proj_b = (const float*)d_in[3];
    const float* eW1    = (const float*)d_in[4];
    const float* eb1    = (const float*)d_in[5];
    const float* eW2    = (const float*)d_in[6];
    const float* eb2    = (const float*)d_in[7];
    const float* nW1    = (const float*)d_in[8];
    const float* nb1    = (const float*)d_in[9];
    const float* nW2    = (const float*)d_in[10];
    const float* nb2    = (const float*)d_in[11];
    const float* cW1    = (const float*)d_in[12];
    const float* cb1    = (const float*)d_in[13];
    const float* cW2    = (const float*)d_in[14];

    cudaFuncSetAttribute(k_edge, cudaFuncAttributeMaxDynamicSharedMemorySize, SMEM_EDGE);
    cudaFuncSetAttribute(k_base, cudaFuncAttributeMaxDynamicSharedMemorySize, SB_BASE);
    cudaFuncSetAttribute(k_node, cudaFuncAttributeMaxDynamicSharedMemorySize, SB_NODE);

    k_center<<<1, NN>>>(anchor);
    k_proj<<<NN, HH>>>(z, proj_W, proj_b);
    for (int l = 0; l < LL; l++) {
        k_base<<<NN / RBB, 256, SB_BASE>>>(eW1, eb1, l);
        k_edge<<<NN, 256, SMEM_EDGE>>>(eW1, eW2, eb2, cW1, cb1, cW2, l);
        k_node<<<NN / RBB, 256, SB_NODE>>>(nW1, nb1, nW2, nb2, l);
    }
    k_out<<<(NN * 3 + 255) / 256, 256>>>((float*)d_out);
}